// round 6
// baseline (speedup 1.0000x reference)
#include <cuda_runtime.h>
#include <cstddef>

// SpanRepresentation: out[b, s, :] = concat(x[b, start(s), :], x[b, end(s), :], wemb[wid(s), :])
// B=16, L=512, D=768, W=8, WD=64. Spans ordered by width w=1..8, then start.
// Pure gather/concat: DRAM-write-bound (417 MB output). This version uses
// sm_103a 256-bit vector loads/stores (LDG.256/STG.256) to halve LSU/L1tex
// work, which was co-binding with DRAM (L1 73% vs DRAM 76%) in the float4 version.

constexpr int B   = 16;
constexpr int L   = 512;
constexpr int D   = 768;
constexpr int WD  = 64;
constexpr int NS  = 4068;            // total spans

constexpr int ROWF = 2 * D + WD;     // 1600 floats per output row
constexpr int ROW8 = ROWF / 8;       // 200 x 32B chunks
constexpr int D8   = D / 8;          // 96
// boundaries at 96 (xs->xe) and 192 (xe->wemb): both warp-aligned under stride 128

__device__ __forceinline__ void ldg_v8(const float* __restrict__ p, float r[8]) {
    asm volatile("ld.global.nc.v8.f32 {%0,%1,%2,%3,%4,%5,%6,%7}, [%8];"
                 : "=f"(r[0]), "=f"(r[1]), "=f"(r[2]), "=f"(r[3]),
                   "=f"(r[4]), "=f"(r[5]), "=f"(r[6]), "=f"(r[7])
                 : "l"(p));
}

__device__ __forceinline__ void stg_cs_v8(float* __restrict__ p, const float r[8]) {
    // .cs = streaming (evict-first): output is touched exactly once; keep x in L2.
    asm volatile("st.global.cs.v8.f32 [%0], {%1,%2,%3,%4,%5,%6,%7,%8};"
                 :: "l"(p),
                    "f"(r[0]), "f"(r[1]), "f"(r[2]), "f"(r[3]),
                    "f"(r[4]), "f"(r[5]), "f"(r[6]), "f"(r[7])
                 : "memory");
}

__global__ __launch_bounds__(128, 16)
void span_repr_kernel(const float* __restrict__ x,      // [B, L, D]
                      const float* __restrict__ wemb,   // [W, WD]
                      float* __restrict__ out)          // [B*NS, ROWF]
{
    const int row = blockIdx.x;          // 0 .. B*NS-1
    const int b   = row / NS;
    const int s   = row - b * NS;

    // Width bucket (block-uniform): cumulative span offsets per width.
    int wid = 0;
    wid += (s >= 512);
    wid += (s >= 1023);
    wid += (s >= 1533);
    wid += (s >= 2042);
    wid += (s >= 2550);
    wid += (s >= 3057);
    wid += (s >= 3563);

    int off;
    switch (wid) {
        case 0: off = 0;    break;
        case 1: off = 512;  break;
        case 2: off = 1023; break;
        case 3: off = 1533; break;
        case 4: off = 2042; break;
        case 5: off = 2550; break;
        case 6: off = 3057; break;
        default: off = 3563; break;
    }
    const int start = s - off;
    const int end   = start + wid;       // width = wid+1

    const float* __restrict__ xs = x    + ((size_t)b * L + start) * D;
    const float* __restrict__ xe = x    + ((size_t)b * L + end)   * D;
    const float* __restrict__ wf = wemb + (size_t)wid * WD;
    float* __restrict__ o        = out  + (size_t)row * ROWF;

    // 200 x 32B per row, stride 128 threads -> 2 iterations (second partial).
    #pragma unroll
    for (int j = threadIdx.x; j < ROW8; j += 128) {
        float v[8];
        if (j < D8) {
            ldg_v8(xs + (size_t)j * 8, v);
        } else if (j < 2 * D8) {
            ldg_v8(xe + (size_t)(j - D8) * 8, v);
        } else {
            ldg_v8(wf + (size_t)(j - 2 * D8) * 8, v);
        }
        stg_cs_v8(o + (size_t)j * 8, v);
    }
}

extern "C" void kernel_launch(void* const* d_in, const int* in_sizes, int n_in,
                              void* d_out, int out_size)
{
    const float* x    = (const float*)d_in[0];   // x: [16, 512, 768] fp32
    const float* wemb = (const float*)d_in[1];   // width_emb: [8, 64] fp32
    float* out        = (float*)d_out;           // [16, 4068, 1600] fp32

    (void)in_sizes; (void)n_in; (void)out_size;

    dim3 grid(B * NS);   // 65088 CTAs, one output row each
    dim3 block(128);
    span_repr_kernel<<<grid, block>>>(x, wemb, out);
}